// round 7
// baseline (speedup 1.0000x reference)
#include <cuda_runtime.h>
#include <math.h>

#define NKNOT 1024
#define NW    1020          // NUM_KNOTS - DEGREE - 1

// fp32 images of +/-pi (np.linspace endpoints after float32 cast)
#define T_LO (-3.14159274101257324218750f)
#define T_HI ( 3.14159274101257324218750f)

// 1023/(2*pi) split hi+lo (hi = correctly-rounded fp32, lo = residual)
#define INVH_HI 162.81578063964843750f
#define INVH_LO (-8.2343605185432045e-08f)
#define S_OFF   511.5f       // pi * 1023/(2*pi), exactly representable

#define THREADS 256
#define ELEMS   8
#define TBL     1032         // 4 zero + 1020 weights + 8 zero

__global__ __launch_bounds__(THREADS) void bspline_act_kernel(
    const float* __restrict__ x,
    const float* __restrict__ w,
    float* __restrict__ out)
{
    // s_big[j+4] = w[j]; zeros at [0..3] and [1024..1031].
    // Tap k of interval i is w[i-3+k] = s_big[i+1+k] — always in range, no clamps.
    __shared__ float s_big[TBL];

    const int tid  = threadIdx.x;
    const int base = (blockIdx.x * THREADS + tid) * ELEMS;

    // ---- prefetch BOTH x vectors first: DRAM latency overlaps prologue + BAR ----
    float4 xa = *reinterpret_cast<const float4*>(x + base);
    float4 xb = *reinterpret_cast<const float4*>(x + base + 4);

    // ---- prologue: pure copy, one float4 per thread ----
    if (tid < NW / 4) {                                         // 255 threads
        reinterpret_cast<float4*>(s_big + 4)[tid] =
            reinterpret_cast<const float4*>(w)[tid];
    } else {                                                    // tid == 255: zero pads
        float4 z = make_float4(0.f, 0.f, 0.f, 0.f);
        reinterpret_cast<float4*>(s_big)[0]   = z;              // [0..3]
        reinterpret_cast<float4*>(s_big)[256] = z;              // [1024..1027]
        reinterpret_cast<float4*>(s_big)[257] = z;              // [1028..1031]
    }
    __syncthreads();

    float xs[8] = {xa.x, xa.y, xa.z, xa.w, xb.x, xb.y, xb.z, xb.w};
    float r[8];

#pragma unroll
    for (int e = 0; e < 8; e++) {
        float xx = xs[e];

        // interval index
        float s1 = fmaf(xx, INVH_HI, S_OFF);
        int i = (int)s1;
        i = min(max(i, 0), NKNOT - 2);

        // compensated local coordinate: 511.5 - i exact; lo-term fixes INVH_HI's
        // representation error. u accurate to ~1e-7 vs ideal uniform grid.
        float offi = S_OFF - (float)i;
        float u = fmaf(xx, INVH_LO, fmaf(xx, INVH_HI, offi));

        // 4 unconditional weight taps (parallel LDS)
        float w0 = s_big[i + 1];
        float w1 = s_big[i + 2];
        float w2 = s_big[i + 3];
        float w3 = s_big[i + 4];

        // uniform cubic B-spline blend
        const float SIXTH = 0.16666666666666666f;
        float omu = 1.0f - u;
        float u2  = u * u;
        float u3  = u2 * u;
        float N0 = omu * omu * omu * SIXTH;
        float N1 = fmaf(3.0f, u3, fmaf(-6.0f, u2, 4.0f)) * SIXTH;
        float N2 = fmaf(-3.0f, u3, fmaf(3.0f, u2, fmaf(3.0f, u, 1.0f))) * SIXTH;
        float N3 = u3 * SIXTH;

        float acc = fmaf(N0, w0, fmaf(N1, w1, fmaf(N2, w2, N3 * w3)));
        r[e] = (xx >= T_LO && xx < T_HI) ? acc : 0.0f;
    }

    *reinterpret_cast<float4*>(out + base)     = make_float4(r[0], r[1], r[2], r[3]);
    *reinterpret_cast<float4*>(out + base + 4) = make_float4(r[4], r[5], r[6], r[7]);
}

extern "C" void kernel_launch(void* const* d_in, const int* in_sizes, int n_in,
                              void* d_out, int out_size) {
    const float* x = (const float*)d_in[0];
    const float* w = (const float*)d_in[1];
    float* out = (float*)d_out;
    int n = in_sizes[0];                         // 262144
    int blocks = n / (THREADS * ELEMS);          // 128, exact cover, one CTA per SM
    bspline_act_kernel<<<blocks, THREADS>>>(x, w, out);
}

// round 8
// speedup vs baseline: 1.0048x; 1.0048x over previous
#include <cuda_runtime.h>
#include <math.h>

#define NKNOT 1024
#define NW    1020          // NUM_KNOTS - DEGREE - 1

// fp32 images of +/-pi (np.linspace endpoints after float32 cast)
#define T_LO (-3.14159274101257324218750f)
#define T_HI ( 3.14159274101257324218750f)

// 1023/(2*pi) split hi+lo (hi = correctly-rounded fp32, lo = residual)
#define INVH_HI 162.81578063964843750f
#define INVH_LO (-8.2343605185432045e-08f)
#define S_OFF   511.5f       // pi * 1023/(2*pi), exactly representable

#define THREADS 128
#define ELEMS   4
#define TBL     1032         // 4 zero + 1020 weights + 8 zero

__global__ __launch_bounds__(THREADS) void bspline_act_kernel(
    const float* __restrict__ x,
    const float* __restrict__ w,
    float* __restrict__ out)
{
    // s_big[j+4] = w[j]; zeros at [0..3] and [1024..1031].
    // Tap k of interval i is w[i-3+k] = s_big[i+1+k] — always in range, no clamps.
    __shared__ float s_big[TBL];

    const int tid  = threadIdx.x;
    const int base = (blockIdx.x * THREADS + tid) * ELEMS;

    // ---- prefetch x FIRST: DRAM latency overlaps prologue + BAR ----
    float4 xv = *reinterpret_cast<const float4*>(x + base);

    // ---- prologue: pure copy, two float4 per thread, loads front-batched ----
    {
        // 1032 floats = 258 float4. Threads 0..254 move two each (510 >= 255+255),
        // covering slots [0..254] and [255..509]? No — use stride layout:
        // slot_a = tid, slot_b = tid + 128; covers [0..255]. Need 258 → last thread
        // also handles slots 256, 257.
        const float4* w4 = reinterpret_cast<const float4*>(w);
        float4* s4 = reinterpret_cast<float4*>(s_big);
        float4 z = make_float4(0.f, 0.f, 0.f, 0.f);

        // shifted table: s_big[4..1023] = w[0..1019] -> float4 slots 1..254 hold
        // w4[slot-1] exactly (16B aligned both sides).
        int sa = tid;               // slots 0..127
        int sb = tid + 128;         // slots 128..255
        float4 va = (sa >= 1 && sa <= 254) ? w4[sa - 1] : z;   // slot 0 = left pad
        float4 vb = (sb <= 254) ? w4[sb - 1] : z;
        if (sa == 0) va = z;
        if (sb == 255) {            // slot 255 = floats 1020..1023: w[1016..1019]
            vb = make_float4(__ldg(w + 1016), __ldg(w + 1017), __ldg(w + 1018), __ldg(w + 1019));
        }
        s4[sa] = va;
        s4[sb] = vb;
        if (tid == 127) {           // slots 256,257 = floats 1024..1031: zero pad
            s4[256] = z;
            s4[257] = z;
        }
        // fix: slot 255 floats are s_big[1020..1023] = w[1016..1019]; but the
        // aligned copy w4[254] wrote s_big[1016..1019] = w[1012..1015]. The
        // shifted-by-4 layout keeps float4 alignment: s_big[4+j]=w[j] means
        // s4[k] (k>=1) = w4[k-1]. Slot 255 = s_big[1020..1023] = w[1016..1019]
        // = w4[254]. So the scalar path above is equivalent; keep simple form.
    }
    __syncthreads();

    float xs[4] = {xv.x, xv.y, xv.z, xv.w};
    float r[4];

#pragma unroll
    for (int e = 0; e < 4; e++) {
        float xx = xs[e];

        // interval index
        float s1 = fmaf(xx, INVH_HI, S_OFF);
        int i = (int)s1;
        i = min(max(i, 0), NKNOT - 2);

        // compensated local coordinate: 511.5 - i exact; lo-term fixes INVH_HI's
        // representation error. u accurate to ~1e-7 vs ideal uniform grid.
        float offi = S_OFF - (float)i;
        float u = fmaf(xx, INVH_LO, fmaf(xx, INVH_HI, offi));

        // 4 unconditional weight taps (parallel LDS)
        float w0 = s_big[i + 1];
        float w1 = s_big[i + 2];
        float w2 = s_big[i + 3];
        float w3 = s_big[i + 4];

        // uniform cubic B-spline blend
        const float SIXTH = 0.16666666666666666f;
        float omu = 1.0f - u;
        float u2  = u * u;
        float u3  = u2 * u;
        float N0 = omu * omu * omu * SIXTH;
        float N1 = fmaf(3.0f, u3, fmaf(-6.0f, u2, 4.0f)) * SIXTH;
        float N2 = fmaf(-3.0f, u3, fmaf(3.0f, u2, fmaf(3.0f, u, 1.0f))) * SIXTH;
        float N3 = u3 * SIXTH;

        float acc = fmaf(N0, w0, fmaf(N1, w1, fmaf(N2, w2, N3 * w3)));
        r[e] = (xx >= T_LO && xx < T_HI) ? acc : 0.0f;
    }

    *reinterpret_cast<float4*>(out + base) = make_float4(r[0], r[1], r[2], r[3]);
}

extern "C" void kernel_launch(void* const* d_in, const int* in_sizes, int n_in,
                              void* d_out, int out_size) {
    const float* x = (const float*)d_in[0];
    const float* w = (const float*)d_in[1];
    float* out = (float*)d_out;
    int n = in_sizes[0];                         // 262144
    int blocks = n / (THREADS * ELEMS);          // 512 CTAs -> 3-4 per SM, low imbalance
    bspline_act_kernel<<<blocks, THREADS>>>(x, w, out);
}